// round 1
// baseline (speedup 1.0000x reference)
#include <cuda_runtime.h>
#include <math.h>
#include <stdint.h>

#define TNUM 2048
#define DDIM 2048
#define FDIM 512
#define ENUM 16
#define TOPK 4

// ---------------- scratch (device globals; no allocations allowed) ----------
__device__ float g_comb_w[TNUM * TOPK];
__device__ int   g_topk[TNUM * TOPK];
__device__ float g_shared_gate[TNUM];
__device__ int   g_counts[ENUM];
__device__ int   g_offsets[ENUM + 1];
__device__ int   g_cursor[ENUM];
__device__ int   g_token_list[TNUM * TOPK];
__device__ float g_weight_list[TNUM * TOPK];
__device__ float g_H[(size_t)TNUM * TOPK * FDIM];   // expert hidden, grouped by expert
__device__ float g_Hs[(size_t)TNUM * FDIM];         // shared-expert hidden

// ---------------- small helpers ---------------------------------------------
__global__ void k_zero_counts() {
    if (threadIdx.x < ENUM) g_counts[threadIdx.x] = 0;
}

// Router: per token, 16 expert logits + shared-gate logit; top-4 softmax.
__global__ void k_router(const float* __restrict__ x,
                         const float* __restrict__ gate_w,
                         const float* __restrict__ sgw) {
    int t = blockIdx.x;
    const float* xr = x + (size_t)t * DDIM;
    float acc[17];
#pragma unroll
    for (int e = 0; e < 17; e++) acc[e] = 0.f;

    for (int d = threadIdx.x; d < DDIM; d += blockDim.x) {
        float xv = xr[d];
#pragma unroll
        for (int e = 0; e < ENUM; e++) acc[e] += xv * gate_w[e * DDIM + d];
        acc[16] += xv * sgw[d];
    }
    // warp reduce
#pragma unroll
    for (int off = 16; off; off >>= 1) {
#pragma unroll
        for (int e = 0; e < 17; e++) acc[e] += __shfl_down_sync(0xffffffffu, acc[e], off);
    }
    __shared__ float red[17][4];
    int warp = threadIdx.x >> 5, lane = threadIdx.x & 31;
    if (lane == 0) {
#pragma unroll
        for (int e = 0; e < 17; e++) red[e][warp] = acc[e];
    }
    __syncthreads();
    if (threadIdx.x == 0) {
        float v[17];
#pragma unroll
        for (int e = 0; e < 17; e++) v[e] = red[e][0] + red[e][1] + red[e][2] + red[e][3];

        // top-4 of logits (softmax-then-topk-then-renorm == softmax over top-4 logits)
        float lv[16];
#pragma unroll
        for (int e = 0; e < ENUM; e++) lv[e] = v[e];
        int   idx[TOPK];
        float lg[TOPK];
#pragma unroll
        for (int k = 0; k < TOPK; k++) {
            int bi = 0; float bv = lv[0];
#pragma unroll
            for (int e = 1; e < ENUM; e++) {
                if (lv[e] > bv) { bv = lv[e]; bi = e; }
            }
            idx[k] = bi; lg[k] = bv; lv[bi] = -1e30f;
        }
        float mx = lg[0];  // first pick is the max
        float s = 0.f;
        float w[TOPK];
#pragma unroll
        for (int k = 0; k < TOPK; k++) { w[k] = expf(lg[k] - mx); s += w[k]; }
        float inv = 1.f / s;
#pragma unroll
        for (int k = 0; k < TOPK; k++) {
            g_topk[t * TOPK + k]   = idx[k];
            g_comb_w[t * TOPK + k] = w[k] * inv;
            atomicAdd(&g_counts[idx[k]], 1);
        }
        g_shared_gate[t] = 1.f / (1.f + expf(-v[16]));
    }
}

__global__ void k_scan() {
    if (threadIdx.x == 0 && blockIdx.x == 0) {
        int o = 0;
        for (int e = 0; e < ENUM; e++) {
            g_offsets[e] = o;
            g_cursor[e]  = o;
            o += g_counts[e];
        }
        g_offsets[ENUM] = o;
    }
}

__global__ void k_scatter() {
    int i = blockIdx.x * blockDim.x + threadIdx.x;
    if (i < TNUM * TOPK) {
        int e = g_topk[i];
        int pos = atomicAdd(&g_cursor[e], 1);
        g_token_list[pos]  = i / TOPK;
        g_weight_list[pos] = g_comb_w[i];
    }
}

// ---------------- fused gate+up SGEMM + SwiGLU -------------------------------
// A[M,D] (gathered token rows) @ Wg/Wu[D,F] -> H = silu(g)*u
template <bool GATHER>
__global__ void __launch_bounds__(256)
k_upgate(const float* __restrict__ x,
         const float* __restrict__ Wg,
         const float* __restrict__ Wu) {
    const int BM = 64, BN = 64, BK = 16;
    int e    = GATHER ? blockIdx.z : 0;
    int seg0 = GATHER ? g_offsets[e] : 0;
    int seg1 = GATHER ? g_offsets[e + 1] : TNUM;
    int r0   = seg0 + blockIdx.x * BM;
    if (r0 >= seg1) return;
    int rows = min(BM, seg1 - r0);
    int f0   = blockIdx.y * BN;

    float* __restrict__ Hout = GATHER ? g_H : g_Hs;

    __shared__ float As[BK][BM + 4];
    __shared__ float Bg[BK][BN + 4];
    __shared__ float Bu[BK][BN + 4];
    __shared__ int   toks[BM];

    int tid = threadIdx.x;
    if (tid < BM) {
        int tok = -1;
        if (tid < rows) tok = GATHER ? g_token_list[r0 + tid] : (r0 + tid);
        toks[tid] = tok;
    }
    __syncthreads();

    const float* Wge = Wg + (size_t)e * DDIM * FDIM;
    const float* Wue = Wu + (size_t)e * DDIM * FDIM;

    float accg[4][4], accu[4][4];
#pragma unroll
    for (int i = 0; i < 4; i++)
#pragma unroll
        for (int j = 0; j < 4; j++) { accg[i][j] = 0.f; accu[i][j] = 0.f; }

    int aCol = tid & 15, aRow0 = tid >> 4;   // 16 rows/pass, 4 passes
    int bCol = tid & 63, bRow0 = tid >> 6;   // 4 k-rows/pass, 4 passes
    int ty = tid >> 4, tx = tid & 15;

    for (int kk = 0; kk < DDIM; kk += BK) {
#pragma unroll
        for (int p = 0; p < 4; p++) {
            int m = aRow0 + p * 16;
            int tok = toks[m];
            As[aCol][m] = (tok >= 0) ? x[(size_t)tok * DDIM + kk + aCol] : 0.f;
        }
#pragma unroll
        for (int p = 0; p < 4; p++) {
            int kr = bRow0 + p * 4;
            size_t off = (size_t)(kk + kr) * FDIM + f0 + bCol;
            Bg[kr][bCol] = Wge[off];
            Bu[kr][bCol] = Wue[off];
        }
        __syncthreads();
#pragma unroll
        for (int k = 0; k < BK; k++) {
            float4 a4 = *reinterpret_cast<const float4*>(&As[k][ty * 4]);
            float4 g4 = *reinterpret_cast<const float4*>(&Bg[k][tx * 4]);
            float4 u4 = *reinterpret_cast<const float4*>(&Bu[k][tx * 4]);
            float a[4] = {a4.x, a4.y, a4.z, a4.w};
            float bg[4] = {g4.x, g4.y, g4.z, g4.w};
            float bu[4] = {u4.x, u4.y, u4.z, u4.w};
#pragma unroll
            for (int i = 0; i < 4; i++)
#pragma unroll
                for (int j = 0; j < 4; j++) {
                    accg[i][j] += a[i] * bg[j];
                    accu[i][j] += a[i] * bu[j];
                }
        }
        __syncthreads();
    }

#pragma unroll
    for (int i = 0; i < 4; i++) {
        int m = ty * 4 + i;
        if (m < rows) {
            float* op = Hout + (size_t)(r0 + m) * FDIM + f0 + tx * 4;
#pragma unroll
            for (int j = 0; j < 4; j++) {
                float g = accg[i][j];
                op[j] = g / (1.f + expf(-g)) * accu[i][j];   // silu(g)*u
            }
        }
    }
}

// ---------------- down-proj SGEMM --------------------------------------------
// H[M,F] @ Wd[F,D]; EXPERT: weighted atomicAdd scatter; shared: gated store.
template <bool EXPERT>
__global__ void __launch_bounds__(256)
k_down(const float* __restrict__ Wd, float* __restrict__ out) {
    const int BM = 64, BN = 64, BK = 16;
    int e    = EXPERT ? blockIdx.z : 0;
    int seg0 = EXPERT ? g_offsets[e] : 0;
    int seg1 = EXPERT ? g_offsets[e + 1] : TNUM;
    int r0   = seg0 + blockIdx.x * BM;
    if (r0 >= seg1) return;
    int rows = min(BM, seg1 - r0);
    int n0   = blockIdx.y * BN;

    const float* __restrict__ Hin = EXPERT ? g_H : g_Hs;

    __shared__ float As[BK][BM + 4];
    __shared__ float Bs[BK][BN + 4];
    __shared__ int   toks[BM];
    __shared__ float wts[BM];

    int tid = threadIdx.x;
    if (tid < BM) {
        if (tid < rows) {
            if (EXPERT) {
                toks[tid] = g_token_list[r0 + tid];
                wts[tid]  = g_weight_list[r0 + tid];
            } else {
                toks[tid] = r0 + tid;
                wts[tid]  = g_shared_gate[r0 + tid];
            }
        } else {
            toks[tid] = -1;
            wts[tid]  = 0.f;
        }
    }
    __syncthreads();

    const float* Wde = Wd + (size_t)e * FDIM * DDIM;

    float acc[4][4];
#pragma unroll
    for (int i = 0; i < 4; i++)
#pragma unroll
        for (int j = 0; j < 4; j++) acc[i][j] = 0.f;

    int aCol = tid & 15, aRow0 = tid >> 4;
    int bCol = tid & 63, bRow0 = tid >> 6;
    int ty = tid >> 4, tx = tid & 15;

    for (int kk = 0; kk < FDIM; kk += BK) {
#pragma unroll
        for (int p = 0; p < 4; p++) {
            int m = aRow0 + p * 16;
            As[aCol][m] = (m < rows) ? Hin[(size_t)(r0 + m) * FDIM + kk + aCol] : 0.f;
        }
#pragma unroll
        for (int p = 0; p < 4; p++) {
            int kr = bRow0 + p * 4;
            Bs[kr][bCol] = Wde[(size_t)(kk + kr) * DDIM + n0 + bCol];
        }
        __syncthreads();
#pragma unroll
        for (int k = 0; k < BK; k++) {
            float4 a4 = *reinterpret_cast<const float4*>(&As[k][ty * 4]);
            float4 b4 = *reinterpret_cast<const float4*>(&Bs[k][tx * 4]);
            float a[4] = {a4.x, a4.y, a4.z, a4.w};
            float b[4] = {b4.x, b4.y, b4.z, b4.w};
#pragma unroll
            for (int i = 0; i < 4; i++)
#pragma unroll
                for (int j = 0; j < 4; j++) acc[i][j] += a[i] * b[j];
        }
        __syncthreads();
    }

#pragma unroll
    for (int i = 0; i < 4; i++) {
        int m = ty * 4 + i;
        if (m < rows) {
            int t = toks[m];
            float w = wts[m];
            float* op = out + (size_t)t * DDIM + n0 + tx * 4;
#pragma unroll
            for (int j = 0; j < 4; j++) {
                if (EXPERT) atomicAdd(&op[j], w * acc[i][j]);
                else        op[j] = w * acc[i][j];
            }
        }
    }
}

// ---------------- launch ------------------------------------------------------
extern "C" void kernel_launch(void* const* d_in, const int* in_sizes, int n_in,
                              void* d_out, int out_size) {
    const float* x   = (const float*)d_in[0];   // hidden_states [1,2048,2048]
    const float* gw  = (const float*)d_in[1];   // gate_w [16,2048]
    const float* Wg  = (const float*)d_in[2];   // [16,2048,512]
    const float* Wu  = (const float*)d_in[3];   // [16,2048,512]
    const float* Wd  = (const float*)d_in[4];   // [16,512,2048]
    const float* sWg = (const float*)d_in[5];   // [2048,512]
    const float* sWu = (const float*)d_in[6];   // [2048,512]
    const float* sWd = (const float*)d_in[7];   // [512,2048]
    const float* sgw = (const float*)d_in[8];   // [2048,1]
    float* out = (float*)d_out;

    (void)in_sizes; (void)n_in; (void)out_size;

    k_zero_counts<<<1, 32>>>();
    k_router<<<TNUM, 128>>>(x, gw, sgw);
    k_scan<<<1, 1>>>();
    k_scatter<<<(TNUM * TOPK + 255) / 256, 256>>>();

    // expert gate/up + swiglu into grouped H
    k_upgate<true><<<dim3(TNUM / 64, FDIM / 64, ENUM), 256>>>(x, Wg, Wu);
    // shared expert gate/up
    k_upgate<false><<<dim3(TNUM / 64, FDIM / 64, 1), 256>>>(x, sWg, sWu);
    // shared expert down-proj initializes the output (gated store)
    k_down<false><<<dim3(TNUM / 64, DDIM / 64, 1), 256>>>(sWd, out);
    // expert down-proj accumulates (weighted atomicAdd)
    k_down<true><<<dim3(TNUM / 64, DDIM / 64, ENUM), 256>>>(Wd, out);
}

// round 2
// speedup vs baseline: 1.5398x; 1.5398x over previous
#include <cuda_runtime.h>
#include <mma.h>
#include <math.h>
#include <stdint.h>

using namespace nvcuda;

#define TNUM 2048
#define DDIM 2048
#define FDIM 512
#define ENUM 16
#define TOPK 4
#define HROWS (TNUM * TOPK + ENUM * 64)   // padded grouped rows

// ---------------- scratch (device globals; no allocations allowed) ----------
__device__ float g_comb_w[TNUM * TOPK];
__device__ int   g_topk[TNUM * TOPK];
__device__ float g_shared_gate[TNUM];
__device__ int   g_counts[ENUM];
__device__ int   g_offsets[ENUM + 1];
__device__ int   g_cursor[ENUM];
__device__ int   g_token_list[HROWS];
__device__ float g_weight_list[HROWS];
__device__ float g_H[(size_t)HROWS * FDIM];    // expert hidden, grouped+padded
__device__ float g_Hs[(size_t)TNUM * FDIM];    // shared-expert hidden

// ---------------- init: zero counts, poison token list -----------------------
__global__ void k_init() {
    int i = blockIdx.x * blockDim.x + threadIdx.x;
    if (i < ENUM) g_counts[i] = 0;
    for (int j = i; j < HROWS; j += gridDim.x * blockDim.x) g_token_list[j] = -1;
}

// ---------------- router: top-4 softmax + shared gate ------------------------
__global__ void k_router(const float* __restrict__ x,
                         const float* __restrict__ gate_w,
                         const float* __restrict__ sgw) {
    int t = blockIdx.x;
    const float* xr = x + (size_t)t * DDIM;
    float acc[17];
#pragma unroll
    for (int e = 0; e < 17; e++) acc[e] = 0.f;

    for (int d = threadIdx.x; d < DDIM; d += blockDim.x) {
        float xv = xr[d];
#pragma unroll
        for (int e = 0; e < ENUM; e++) acc[e] += xv * gate_w[e * DDIM + d];
        acc[16] += xv * sgw[d];
    }
#pragma unroll
    for (int off = 16; off; off >>= 1) {
#pragma unroll
        for (int e = 0; e < 17; e++) acc[e] += __shfl_down_sync(0xffffffffu, acc[e], off);
    }
    __shared__ float red[17][4];
    int warp = threadIdx.x >> 5, lane = threadIdx.x & 31;
    if (lane == 0) {
#pragma unroll
        for (int e = 0; e < 17; e++) red[e][warp] = acc[e];
    }
    __syncthreads();
    if (threadIdx.x == 0) {
        float v[17];
#pragma unroll
        for (int e = 0; e < 17; e++) v[e] = red[e][0] + red[e][1] + red[e][2] + red[e][3];

        float lv[16];
#pragma unroll
        for (int e = 0; e < ENUM; e++) lv[e] = v[e];
        int   idx[TOPK];
        float lg[TOPK];
#pragma unroll
        for (int k = 0; k < TOPK; k++) {
            int bi = 0; float bv = lv[0];
#pragma unroll
            for (int e = 1; e < ENUM; e++) if (lv[e] > bv) { bv = lv[e]; bi = e; }
            idx[k] = bi; lg[k] = bv; lv[bi] = -1e30f;
        }
        float mx = lg[0], s = 0.f, w[TOPK];
#pragma unroll
        for (int k = 0; k < TOPK; k++) { w[k] = expf(lg[k] - mx); s += w[k]; }
        float inv = 1.f / s;
#pragma unroll
        for (int k = 0; k < TOPK; k++) {
            g_topk[t * TOPK + k]   = idx[k];
            g_comb_w[t * TOPK + k] = w[k] * inv;
            atomicAdd(&g_counts[idx[k]], 1);
        }
        g_shared_gate[t] = 1.f / (1.f + expf(-v[16]));
    }
}

__global__ void k_scan() {
    if (threadIdx.x == 0 && blockIdx.x == 0) {
        int o = 0;
        for (int e = 0; e < ENUM; e++) {
            g_offsets[e] = o;
            g_cursor[e]  = o;
            o += (g_counts[e] + 63) & ~63;   // pad segments to 64 rows
        }
        g_offsets[ENUM] = o;
    }
}

__global__ void k_scatter() {
    int i = blockIdx.x * blockDim.x + threadIdx.x;
    if (i < TNUM * TOPK) {
        int e = g_topk[i];
        int pos = atomicAdd(&g_cursor[e], 1);
        g_token_list[pos]  = i / TOPK;
        g_weight_list[pos] = g_comb_w[i];
    }
}

// ---------------- tf32 wmma fused gate+up + SwiGLU ---------------------------
// A[64 rows gathered, D] @ Wg/Wu[D, F-tile 64] -> H = silu(g)*u (in-register)
template <bool GATHER>
__global__ void __launch_bounds__(256)
k_upgate_tc(const float* __restrict__ x,
            const float* __restrict__ Wg,
            const float* __restrict__ Wu) {
    const int BM = 64, BN = 64, BK = 32;
    int e    = GATHER ? blockIdx.z : 0;
    int seg0 = GATHER ? g_offsets[e] : 0;
    int seg1 = GATHER ? g_offsets[e + 1] : TNUM;
    int r0   = seg0 + blockIdx.x * BM;
    if (r0 >= seg1) return;
    int f0 = blockIdx.y * BN;

    float* __restrict__ Hout = GATHER ? g_H : g_Hs;

    __shared__ float As[BM][BK + 4];      // 64 x 36
    __shared__ float Bgs[BK][BN + 4];     // 32 x 68
    __shared__ float Bus[BK][BN + 4];
    __shared__ int   toks[BM];

    int tid = threadIdx.x;
    if (tid < BM) toks[tid] = GATHER ? g_token_list[r0 + tid] : (r0 + tid);
    __syncthreads();

    const float* Wge = Wg + (size_t)e * DDIM * FDIM;
    const float* Wue = Wu + (size_t)e * DDIM * FDIM;

    wmma::fragment<wmma::matrix_a, 16, 16, 8, wmma::precision::tf32, wmma::row_major> af;
    wmma::fragment<wmma::matrix_b, 16, 16, 8, wmma::precision::tf32, wmma::row_major> bf;
    wmma::fragment<wmma::accumulator, 16, 16, 8, float> cg[2], cu[2];
#pragma unroll
    for (int nf = 0; nf < 2; nf++) { wmma::fill_fragment(cg[nf], 0.f); wmma::fill_fragment(cu[nf], 0.f); }

    int warp = tid >> 5;
    int wm = warp & 3;       // 4 warps over M (16 rows each)
    int wn = warp >> 2;      // 2 warps over N (32 cols each)

    for (int kk = 0; kk < DDIM; kk += BK) {
        // A: 64x32 = 512 float4, 2 per thread (gathered rows)
#pragma unroll
        for (int p = 0; p < 2; p++) {
            int idx = tid + p * 256;
            int row = idx >> 3, c4 = idx & 7;
            int tok = toks[row];
            float4 v = make_float4(0.f, 0.f, 0.f, 0.f);
            if (tok >= 0) v = *reinterpret_cast<const float4*>(&x[(size_t)tok * DDIM + kk + c4 * 4]);
            *reinterpret_cast<float4*>(&As[row][c4 * 4]) = v;
        }
        // Bg/Bu: 32x64 = 512 float4 each, 2 per thread
#pragma unroll
        for (int p = 0; p < 2; p++) {
            int idx = tid + p * 256;
            int kr = idx >> 4, c4 = idx & 15;
            size_t off = (size_t)(kk + kr) * FDIM + f0 + c4 * 4;
            *reinterpret_cast<float4*>(&Bgs[kr][c4 * 4]) = *reinterpret_cast<const float4*>(&Wge[off]);
            *reinterpret_cast<float4*>(&Bus[kr][c4 * 4]) = *reinterpret_cast<const float4*>(&Wue[off]);
        }
        __syncthreads();

#pragma unroll
        for (int ks = 0; ks < 4; ks++) {
            wmma::load_matrix_sync(af, &As[wm * 16][ks * 8], BK + 4);
#pragma unroll
            for (int i = 0; i < af.num_elements; i++) af.x[i] = wmma::__float_to_tf32(af.x[i]);
#pragma unroll
            for (int nf = 0; nf < 2; nf++) {
                wmma::load_matrix_sync(bf, &Bgs[ks * 8][wn * 32 + nf * 16], BN + 4);
#pragma unroll
                for (int i = 0; i < bf.num_elements; i++) bf.x[i] = wmma::__float_to_tf32(bf.x[i]);
                wmma::mma_sync(cg[nf], af, bf, cg[nf]);

                wmma::load_matrix_sync(bf, &Bus[ks * 8][wn * 32 + nf * 16], BN + 4);
#pragma unroll
                for (int i = 0; i < bf.num_elements; i++) bf.x[i] = wmma::__float_to_tf32(bf.x[i]);
                wmma::mma_sync(cu[nf], af, bf, cu[nf]);
            }
        }
        __syncthreads();
    }

    // SwiGLU in-register (cg/cu share element mapping), store to grouped H.
    int mrow = r0 + wm * 16;
#pragma unroll
    for (int nf = 0; nf < 2; nf++) {
#pragma unroll
        for (int i = 0; i < cg[nf].num_elements; i++) {
            float g = cg[nf].x[i];
            cg[nf].x[i] = g / (1.f + expf(-g)) * cu[nf].x[i];
        }
        wmma::store_matrix_sync(Hout + (size_t)mrow * FDIM + f0 + wn * 32 + nf * 16,
                                cg[nf], FDIM, wmma::mem_row_major);
    }
}

// ---------------- tf32 wmma down-proj ----------------------------------------
// H[64, F] @ Wd[F, D-tile 64]; EXPERT: weighted atomicAdd; shared: gated store.
template <bool EXPERT>
__global__ void __launch_bounds__(256)
k_down_tc(const float* __restrict__ Wd, float* __restrict__ out) {
    const int BM = 64, BN = 64, BK = 32;
    int e    = EXPERT ? blockIdx.z : 0;
    int seg0 = EXPERT ? g_offsets[e] : 0;
    int seg1 = EXPERT ? g_offsets[e + 1] : TNUM;
    int r0   = seg0 + blockIdx.x * BM;
    if (r0 >= seg1) return;
    int n0 = blockIdx.y * BN;

    const float* __restrict__ Hin = EXPERT ? g_H : g_Hs;

    __shared__ float As[BM][BK + 4];      // 64 x 36
    __shared__ float Bs[BK][BN + 4];      // 32 x 68
    __shared__ float Ss[BM][BN + 4];      // 64 x 68 staging
    __shared__ int   toks[BM];
    __shared__ float wts[BM];

    int tid = threadIdx.x;
    if (tid < BM) {
        if (EXPERT) {
            toks[tid] = g_token_list[r0 + tid];       // -1 in padding
            wts[tid]  = g_weight_list[r0 + tid];
        } else {
            toks[tid] = r0 + tid;
            wts[tid]  = g_shared_gate[r0 + tid];
        }
    }
    __syncthreads();

    const float* Wde = Wd + (size_t)e * FDIM * DDIM;

    wmma::fragment<wmma::matrix_a, 16, 16, 8, wmma::precision::tf32, wmma::row_major> af;
    wmma::fragment<wmma::matrix_b, 16, 16, 8, wmma::precision::tf32, wmma::row_major> bf;
    wmma::fragment<wmma::accumulator, 16, 16, 8, float> c[2];
#pragma unroll
    for (int nf = 0; nf < 2; nf++) wmma::fill_fragment(c[nf], 0.f);

    int warp = tid >> 5;
    int wm = warp & 3;
    int wn = warp >> 2;

    for (int kk = 0; kk < FDIM; kk += BK) {
#pragma unroll
        for (int p = 0; p < 2; p++) {
            int idx = tid + p * 256;
            int row = idx >> 3, c4 = idx & 7;
            *reinterpret_cast<float4*>(&As[row][c4 * 4]) =
                *reinterpret_cast<const float4*>(&Hin[(size_t)(r0 + row) * FDIM + kk + c4 * 4]);
        }
#pragma unroll
        for (int p = 0; p < 2; p++) {
            int idx = tid + p * 256;
            int kr = idx >> 4, c4 = idx & 15;
            *reinterpret_cast<float4*>(&Bs[kr][c4 * 4]) =
                *reinterpret_cast<const float4*>(&Wde[(size_t)(kk + kr) * DDIM + n0 + c4 * 4]);
        }
        __syncthreads();

#pragma unroll
        for (int ks = 0; ks < 4; ks++) {
            wmma::load_matrix_sync(af, &As[wm * 16][ks * 8], BK + 4);
#pragma unroll
            for (int i = 0; i < af.num_elements; i++) af.x[i] = wmma::__float_to_tf32(af.x[i]);
#pragma unroll
            for (int nf = 0; nf < 2; nf++) {
                wmma::load_matrix_sync(bf, &Bs[ks * 8][wn * 32 + nf * 16], BN + 4);
#pragma unroll
                for (int i = 0; i < bf.num_elements; i++) bf.x[i] = wmma::__float_to_tf32(bf.x[i]);
                wmma::mma_sync(c[nf], af, bf, c[nf]);
            }
        }
        __syncthreads();
    }

    // stage tile, then weighted scatter
#pragma unroll
    for (int nf = 0; nf < 2; nf++)
        wmma::store_matrix_sync(&Ss[wm * 16][wn * 32 + nf * 16], c[nf], BN + 4, wmma::mem_row_major);
    __syncthreads();

    for (int idx = tid; idx < BM * BN; idx += 256) {
        int m = idx >> 6, n = idx & 63;
        int t = toks[m];
        if (t >= 0) {
            float val = wts[m] * Ss[m][n];
            if (EXPERT) atomicAdd(&out[(size_t)t * DDIM + n0 + n], val);
            else        out[(size_t)t * DDIM + n0 + n] = val;
        }
    }
}

// ---------------- launch ------------------------------------------------------
extern "C" void kernel_launch(void* const* d_in, const int* in_sizes, int n_in,
                              void* d_out, int out_size) {
    const float* x   = (const float*)d_in[0];
    const float* gw  = (const float*)d_in[1];
    const float* Wg  = (const float*)d_in[2];
    const float* Wu  = (const float*)d_in[3];
    const float* Wd  = (const float*)d_in[4];
    const float* sWg = (const float*)d_in[5];
    const float* sWu = (const float*)d_in[6];
    const float* sWd = (const float*)d_in[7];
    const float* sgw = (const float*)d_in[8];
    float* out = (float*)d_out;

    (void)in_sizes; (void)n_in; (void)out_size;

    k_init<<<8, 256>>>();
    k_router<<<TNUM, 128>>>(x, gw, sgw);
    k_scan<<<1, 1>>>();
    k_scatter<<<(TNUM * TOPK + 255) / 256, 256>>>();

    k_upgate_tc<true><<<dim3(TNUM / 64, FDIM / 64, ENUM), 256>>>(x, Wg, Wu);
    k_upgate_tc<false><<<dim3(TNUM / 64, FDIM / 64, 1), 256>>>(x, sWg, sWu);
    k_down_tc<false><<<dim3(TNUM / 64, DDIM / 64, 1), 256>>>(sWd, out);
    k_down_tc<true><<<dim3(TNUM / 64, DDIM / 64, ENUM), 256>>>(Wd, out);
}

// round 6
// speedup vs baseline: 3.7004x; 2.4031x over previous
#include <cuda_runtime.h>
#include <math.h>
#include <stdint.h>

#define TNUM 2048
#define DDIM 2048
#define FDIM 512
#define ENUM 16
#define TOPK 4
#define MT   128
#define SH0  (TNUM * TOPK + ENUM * MT)   // 10240
#define HROWS (SH0 + TNUM)               // 12288
#define MAXT (HROWS / MT)                // 96

// ---------------- device scratch -------------------------------------------
__device__ float g_comb_w[TNUM * TOPK];
__device__ int   g_topk[TNUM * TOPK];
__device__ int   g_counts[ENUM];
__device__ int   g_offsets[ENUM + 1];
__device__ int   g_cursor[ENUM];
__device__ int   g_token_list[HROWS];
__device__ float g_weight_list[HROWS];
__device__ int   g_pos_of[TNUM * TOPK];
__device__ int   g_tile_seg[MAXT];
__device__ int   g_tile_r0[MAXT];
__device__ int   g_ntiles;
__device__ float g_H[(size_t)HROWS * FDIM];
__device__ float g_partial[(size_t)HROWS * DDIM];
// tf32-rounded copies (original layouts)
__device__ float g_Xr[(size_t)TNUM * DDIM];
__device__ float g_Wgr[(size_t)ENUM * DDIM * FDIM];
__device__ float g_Wur[(size_t)ENUM * DDIM * FDIM];
__device__ float g_Wdr[(size_t)ENUM * FDIM * DDIM];
__device__ float g_sWgr[(size_t)DDIM * FDIM];
__device__ float g_sWur[(size_t)DDIM * FDIM];
__device__ float g_sWdr[(size_t)FDIM * DDIM];

// ---------------- helpers ----------------------------------------------------
__device__ __forceinline__ uint32_t smem_u32(const void* p) {
    uint32_t a;
    asm("{ .reg .u64 t; cvta.to.shared.u64 t, %1; cvt.u32.u64 %0, t; }" : "=r"(a) : "l"(p));
    return a;
}
__device__ __forceinline__ float tf32_rna(float v) {
    float o;
    asm("cvt.rna.tf32.f32 %0, %1;" : "=f"(o) : "f"(v));
    return o;
}
__device__ __forceinline__ void cpa16(uint32_t dst, const void* src, bool valid) {
    int sz = valid ? 16 : 0;
    asm volatile("cp.async.cg.shared.global [%0], [%1], 16, %2;"
                 :: "r"(dst), "l"(src), "r"(sz) : "memory");
}
#define CP_COMMIT() asm volatile("cp.async.commit_group;" ::: "memory")
#define CP_WAIT(n)  asm volatile("cp.async.wait_group %0;" :: "n"(n) : "memory")

#define MMA_TF32(C, A, b0, b1)                                                  \
    asm volatile("mma.sync.aligned.m16n8k8.row.col.f32.tf32.tf32.f32 "          \
                 "{%0,%1,%2,%3}, {%4,%5,%6,%7}, {%8,%9}, {%0,%1,%2,%3};"        \
                 : "+f"((C)[0]), "+f"((C)[1]), "+f"((C)[2]), "+f"((C)[3])       \
                 : "r"((A)[0]), "r"((A)[1]), "r"((A)[2]), "r"((A)[3]),          \
                   "r"(b0), "r"(b1))

__device__ __forceinline__ uint32_t fbits(float v) { return __float_as_uint(v); }
__device__ __forceinline__ float silu_mul(float g, float u) {
    return g / (1.f + expf(-g)) * u;
}

// ---------------- tf32 rounding pre-pass -------------------------------------
__global__ void k_cvt(const float4* __restrict__ src, float4* __restrict__ dst, int n4) {
    int i = blockIdx.x * blockDim.x + threadIdx.x;
    if (i < n4) {
        float4 v = src[i];
        v.x = tf32_rna(v.x); v.y = tf32_rna(v.y);
        v.z = tf32_rna(v.z); v.w = tf32_rna(v.w);
        dst[i] = v;
    }
}

// ---------------- init / router / scan / scatter -----------------------------
__global__ void k_init() {
    int i = blockIdx.x * blockDim.x + threadIdx.x;
    if (i < ENUM) g_counts[i] = 0;
    for (int j = i; j < SH0; j += gridDim.x * blockDim.x) g_token_list[j] = -1;
    for (int j = i; j < TNUM; j += gridDim.x * blockDim.x) g_token_list[SH0 + j] = j;
}

__global__ void k_router(const float* __restrict__ x,
                         const float* __restrict__ gate_w,
                         const float* __restrict__ sgw) {
    int t = blockIdx.x;
    const float* xr = x + (size_t)t * DDIM;
    float acc[17];
#pragma unroll
    for (int e = 0; e < 17; e++) acc[e] = 0.f;
    for (int d = threadIdx.x; d < DDIM; d += blockDim.x) {
        float xv = xr[d];
#pragma unroll
        for (int e = 0; e < ENUM; e++) acc[e] += xv * gate_w[e * DDIM + d];
        acc[16] += xv * sgw[d];
    }
#pragma unroll
    for (int off = 16; off; off >>= 1)
#pragma unroll
        for (int e = 0; e < 17; e++) acc[e] += __shfl_down_sync(0xffffffffu, acc[e], off);
    __shared__ float red[17][4];
    int warp = threadIdx.x >> 5, lane = threadIdx.x & 31;
    if (lane == 0)
#pragma unroll
        for (int e = 0; e < 17; e++) red[e][warp] = acc[e];
    __syncthreads();
    if (threadIdx.x == 0) {
        float v[17];
#pragma unroll
        for (int e = 0; e < 17; e++) v[e] = red[e][0] + red[e][1] + red[e][2] + red[e][3];
        float lv[16];
#pragma unroll
        for (int e = 0; e < ENUM; e++) lv[e] = v[e];
        int idx[TOPK]; float lg[TOPK];
#pragma unroll
        for (int k = 0; k < TOPK; k++) {
            int bi = 0; float bv = lv[0];
#pragma unroll
            for (int e = 1; e < ENUM; e++) if (lv[e] > bv) { bv = lv[e]; bi = e; }
            idx[k] = bi; lg[k] = bv; lv[bi] = -1e30f;
        }
        float mx = lg[0], s = 0.f, w[TOPK];
#pragma unroll
        for (int k = 0; k < TOPK; k++) { w[k] = expf(lg[k] - mx); s += w[k]; }
        float inv = 1.f / s;
#pragma unroll
        for (int k = 0; k < TOPK; k++) {
            g_topk[t * TOPK + k]   = idx[k];
            g_comb_w[t * TOPK + k] = w[k] * inv;
            atomicAdd(&g_counts[idx[k]], 1);
        }
        g_weight_list[SH0 + t] = 1.f / (1.f + expf(-v[16]));
    }
}

__global__ void k_scan() {
    if (threadIdx.x == 0 && blockIdx.x == 0) {
        int o = 0, nt = 0;
        for (int e = 0; e < ENUM; e++) {
            g_offsets[e] = o;
            g_cursor[e]  = o;
            int c = (g_counts[e] + MT - 1) & ~(MT - 1);
            for (int r = 0; r < c; r += MT) { g_tile_seg[nt] = e; g_tile_r0[nt] = o + r; nt++; }
            o += c;
        }
        g_offsets[ENUM] = o;
        for (int r = 0; r < TNUM; r += MT) { g_tile_seg[nt] = ENUM; g_tile_r0[nt] = SH0 + r; nt++; }
        g_ntiles = nt;
    }
}

__global__ void k_scatter() {
    int i = blockIdx.x * blockDim.x + threadIdx.x;
    if (i < TNUM * TOPK) {
        int e = g_topk[i];
        int pos = atomicAdd(&g_cursor[e], 1);
        g_token_list[pos]  = i / TOPK;
        g_weight_list[pos] = g_comb_w[i];
        g_pos_of[i]        = pos;
    }
}

// ---------------- upgate: H = silu(X@Wg) * (X@Wu)  (mma.sync tf32) -----------
// Block: 128 rows x 64 F-cols (gate + up). 8 warps = 4(M) x 2(F), warp 32x32x2.
// SMEM byte layout (per stage): A[128][36f] str 144B; Bg/Bu[32][72f] str 288B.
#define UA_STR 36
#define UB_STR 72
#define UA_BUF (128 * 144)          // 18432 B
#define UB_BUF (32 * 288)           // 9216 B
#define U_SMEM (2 * UA_BUF + 4 * UB_BUF)   // 73728 B

__global__ void __launch_bounds__(256, 2)
k_upgate() {
    int ti = blockIdx.x;
    if (ti >= g_ntiles) return;
    int z  = g_tile_seg[ti];
    int r0 = g_tile_r0[ti];
    int f0 = blockIdx.y * 64;

    const float* Wg = (z == ENUM) ? g_sWgr : g_Wgr + (size_t)z * DDIM * FDIM;
    const float* Wu = (z == ENUM) ? g_sWur : g_Wur + (size_t)z * DDIM * FDIM;

    extern __shared__ float smf[];
    uint32_t smb = smem_u32(smf);
    __shared__ int s_tok[MT];

    int tid = threadIdx.x, lane = tid & 31;
    int warp = tid >> 5, wm = warp & 3, wf = warp >> 2;
    int g = lane >> 2, t = lane & 3;

    if (tid < MT) s_tok[tid] = g_token_list[r0 + tid];
    __syncthreads();

    float Cg[2][4][4], Cu[2][4][4];
#pragma unroll
    for (int mt = 0; mt < 2; mt++)
#pragma unroll
        for (int nt = 0; nt < 4; nt++)
#pragma unroll
            for (int q = 0; q < 4; q++) { Cg[mt][nt][q] = 0.f; Cu[mt][nt][q] = 0.f; }

#define U_LOAD(i)                                                               \
    do {                                                                        \
        int s_ = (i) & 1; int kk_ = (i) * 32;                                   \
        uint32_t a_  = smb + s_ * UA_BUF;                                       \
        uint32_t bg_ = smb + 2 * UA_BUF + s_ * UB_BUF;                          \
        uint32_t bu_ = smb + 2 * UA_BUF + 2 * UB_BUF + s_ * UB_BUF;             \
        _Pragma("unroll")                                                       \
        for (int p = 0; p < 4; p++) {                                           \
            int idx = tid + p * 256;                                            \
            int row = idx >> 3, ch = idx & 7;                                   \
            int tok = s_tok[row];                                               \
            const float* src = g_Xr + (size_t)(tok < 0 ? 0 : tok) * DDIM + kk_ + ch * 4; \
            cpa16(a_ + row * 144 + ch * 16, src, tok >= 0);                     \
        }                                                                       \
        _Pragma("unroll")                                                       \
        for (int p = 0; p < 2; p++) {                                           \
            int idx = tid + p * 256;                                            \
            int row = idx >> 4, ch = idx & 15;                                  \
            cpa16(bg_ + row * 288 + ch * 16, Wg + (size_t)(kk_ + row) * FDIM + f0 + ch * 4, true); \
            cpa16(bu_ + row * 288 + ch * 16, Wu + (size_t)(kk_ + row) * FDIM + f0 + ch * 4, true); \
        }                                                                       \
        CP_COMMIT();                                                            \
    } while (0)

    const int NIT = DDIM / 32;   // 64
    U_LOAD(0);
    U_LOAD(1);
    for (int i = 0; i < NIT; i++) {
        if (i + 1 < NIT) CP_WAIT(1); else CP_WAIT(0);
        __syncthreads();
        int s = i & 1;
        const float* As  = smf + (s * UA_BUF) / 4;
        const float* Bgs = smf + (2 * UA_BUF + s * UB_BUF) / 4;
        const float* Bus = smf + (2 * UA_BUF + 2 * UB_BUF + s * UB_BUF) / 4;
#pragma unroll
        for (int ks = 0; ks < 4; ks++) {
            int kb = ks * 8;
            uint32_t a[2][4];
#pragma unroll
            for (int mt = 0; mt < 2; mt++) {
                const float* ab = As + (wm * 32 + mt * 16) * UA_STR + kb;
                a[mt][0] = fbits(ab[g * UA_STR + t]);
                a[mt][1] = fbits(ab[(g + 8) * UA_STR + t]);
                a[mt][2] = fbits(ab[g * UA_STR + t + 4]);
                a[mt][3] = fbits(ab[(g + 8) * UA_STR + t + 4]);
            }
#pragma unroll
            for (int nt = 0; nt < 4; nt++) {
                int nb = wf * 32 + nt * 8 + g;
                uint32_t bg0 = fbits(Bgs[(kb + t) * UB_STR + nb]);
                uint32_t bg1 = fbits(Bgs[(kb + t + 4) * UB_STR + nb]);
                MMA_TF32(Cg[0][nt], a[0], bg0, bg1);
                MMA_TF32(Cg[1][nt], a[1], bg0, bg1);
                uint32_t bu0 = fbits(Bus[(kb + t) * UB_STR + nb]);
                uint32_t bu1 = fbits(Bus[(kb + t + 4) * UB_STR + nb]);
                MMA_TF32(Cu[0][nt], a[0], bu0, bu1);
                MMA_TF32(Cu[1][nt], a[1], bu0, bu1);
            }
        }
        __syncthreads();
        if (i + 2 < NIT) U_LOAD(i + 2);
    }
#undef U_LOAD

    // epilogue: SwiGLU in-register, tf32-round for the down GEMM, store float2
#pragma unroll
    for (int mt = 0; mt < 2; mt++) {
        int m0 = r0 + wm * 32 + mt * 16 + g;
#pragma unroll
        for (int nt = 0; nt < 4; nt++) {
            int f = f0 + wf * 32 + nt * 8 + t * 2;
            float2 v;
            v.x = tf32_rna(silu_mul(Cg[mt][nt][0], Cu[mt][nt][0]));
            v.y = tf32_rna(silu_mul(Cg[mt][nt][1], Cu[mt][nt][1]));
            *reinterpret_cast<float2*>(g_H + (size_t)m0 * FDIM + f) = v;
            v.x = tf32_rna(silu_mul(Cg[mt][nt][2], Cu[mt][nt][2]));
            v.y = tf32_rna(silu_mul(Cg[mt][nt][3], Cu[mt][nt][3]));
            *reinterpret_cast<float2*>(g_H + (size_t)(m0 + 8) * FDIM + f) = v;
        }
    }
}

// ---------------- down: partial = w * (H @ Wd)  (mma.sync tf32) --------------
// Block: 128 rows x 128 D-cols. 8 warps = 4(M) x 2(N), warp 32x64.
// SMEM: A[128][36f] str 144B; B[32][136f] str 544B.
#define DB_STR 136
#define DB_BUF (32 * 544)           // 17408 B
#define D_SMEM (2 * UA_BUF + 2 * DB_BUF)   // 71680 B

__global__ void __launch_bounds__(256, 2)
k_down() {
    int ti = blockIdx.x;
    if (ti >= g_ntiles) return;
    int z  = g_tile_seg[ti];
    int r0 = g_tile_r0[ti];
    int n0 = blockIdx.y * 128;

    const float* Wd = (z == ENUM) ? g_sWdr : g_Wdr + (size_t)z * FDIM * DDIM;

    extern __shared__ float smf[];
    uint32_t smb = smem_u32(smf);

    int tid = threadIdx.x, lane = tid & 31;
    int warp = tid >> 5, wm = warp & 3, wn = warp >> 2;
    int g = lane >> 2, t = lane & 3;

    float C[2][8][4];
#pragma unroll
    for (int mt = 0; mt < 2; mt++)
#pragma unroll
        for (int nt = 0; nt < 8; nt++)
#pragma unroll
            for (int q = 0; q < 4; q++) C[mt][nt][q] = 0.f;

#define D_LOAD(i)                                                               \
    do {                                                                        \
        int s_ = (i) & 1; int kk_ = (i) * 32;                                   \
        uint32_t a_ = smb + s_ * UA_BUF;                                        \
        uint32_t b_ = smb + 2 * UA_BUF + s_ * DB_BUF;                           \
        _Pragma("unroll")                                                       \
        for (int p = 0; p < 4; p++) {                                           \
            int idx = tid + p * 256;                                            \
            int row = idx >> 3, ch = idx & 7;                                   \
            cpa16(a_ + row * 144 + ch * 16,                                     \
                  g_H + (size_t)(r0 + row) * FDIM + kk_ + ch * 4, true);        \
        }                                                                       \
        _Pragma("unroll")                                                       \
        for (int p = 0; p < 4; p++) {                                           \
            int idx = tid + p * 256;                                            \
            int row = idx >> 5, ch = idx & 31;                                  \
            cpa16(b_ + row * 544 + ch * 16,                                     \
                  Wd + (size_t)(kk_ + row) * DDIM + n0 + ch * 4, true);         \
        }                                                                       \
        CP_COMMIT();                                                            \
    } while (0)

    const int NIT = FDIM / 32;   // 16
    D_LOAD(0);
    D_LOAD(1);
    for (int i = 0; i < NIT; i++) {
        if (i + 1 < NIT) CP_WAIT(1); else CP_WAIT(0);
        __syncthreads();
        int s = i & 1;
        const float* As = smf + (s * UA_BUF) / 4;
        const float* Bs = smf + (2 * UA_BUF + s * DB_BUF) / 4;
#pragma unroll
        for (int ks = 0; ks < 4; ks++) {
            int kb = ks * 8;
            uint32_t a[2][4];
#pragma unroll
            for (int mt = 0; mt < 2; mt++) {
                const float* ab = As + (wm * 32 + mt * 16) * UA_STR + kb;
                a[mt][0] = fbits(ab[g * UA_STR + t]);
                a[mt][1] = fbits(ab[(g + 8) * UA_STR + t]);
                a[mt][2] = fbits(ab[g * UA_STR + t + 4]);
                a[mt][3] = fbits(ab[(g + 8) * UA_STR + t + 4]);
            }
#pragma unroll
            for (int nt = 0; nt < 8; nt++) {
                int nb = wn * 64 + nt * 8 + g;
                uint32_t b0 = fbits(Bs[(kb + t) * DB_STR + nb]);
                uint32_t b1 = fbits(Bs[(kb + t + 4) * DB_STR + nb]);
                MMA_TF32(C[0][nt], a[0], b0, b1);
                MMA_TF32(C[1][nt], a[1], b0, b1);
            }
        }
        __syncthreads();
        if (i + 2 < NIT) D_LOAD(i + 2);
    }
#undef D_LOAD

    // epilogue: scale by routing/shared weight, store partial rows
#pragma unroll
    for (int mt = 0; mt < 2; mt++) {
        int m0 = r0 + wm * 32 + mt * 16 + g;
        float w0 = g_weight_list[m0];
        float w1 = g_weight_list[m0 + 8];
#pragma unroll
        for (int nt = 0; nt < 8; nt++) {
            int n = n0 + wn * 64 + nt * 8 + t * 2;
            float2 v;
            v.x = w0 * C[mt][nt][0];
            v.y = w0 * C[mt][nt][1];
            *reinterpret_cast<float2*>(g_partial + (size_t)m0 * DDIM + n) = v;
            v.x = w1 * C[mt][nt][2];
            v.y = w1 * C[mt][nt][3];
            *reinterpret_cast<float2*>(g_partial + (size_t)(m0 + 8) * DDIM + n) = v;
        }
    }
}

// ---------------- combine ----------------------------------------------------
__global__ void k_combine(float* __restrict__ out) {
    int t = blockIdx.x;
    int p0 = g_pos_of[t * TOPK + 0];
    int p1 = g_pos_of[t * TOPK + 1];
    int p2 = g_pos_of[t * TOPK + 2];
    int p3 = g_pos_of[t * TOPK + 3];
    const float4* a0 = (const float4*)(g_partial + (size_t)p0 * DDIM);
    const float4* a1 = (const float4*)(g_partial + (size_t)p1 * DDIM);
    const float4* a2 = (const float4*)(g_partial + (size_t)p2 * DDIM);
    const float4* a3 = (const float4*)(g_partial + (size_t)p3 * DDIM);
    const float4* as = (const float4*)(g_partial + (size_t)(SH0 + t) * DDIM);
    float4* o = (float4*)(out + (size_t)t * DDIM);
    for (int d = threadIdx.x; d < DDIM / 4; d += blockDim.x) {
        float4 v0 = a0[d], v1 = a1[d], v2 = a2[d], v3 = a3[d], vs = as[d];
        float4 r;
        r.x = v0.x + v1.x + v2.x + v3.x + vs.x;
        r.y = v0.y + v1.y + v2.y + v3.y + vs.y;
        r.z = v0.z + v1.z + v2.z + v3.z + vs.z;
        r.w = v0.w + v1.w + v2.w + v3.w + vs.w;
        o[d] = r;
    }
}

// ---------------- launch ------------------------------------------------------
extern "C" void kernel_launch(void* const* d_in, const int* in_sizes, int n_in,
                              void* d_out, int out_size) {
    const float* x   = (const float*)d_in[0];
    const float* gw  = (const float*)d_in[1];
    const float* Wg  = (const float*)d_in[2];
    const float* Wu  = (const float*)d_in[3];
    const float* Wd  = (const float*)d_in[4];
    const float* sWg = (const float*)d_in[5];
    const float* sWu = (const float*)d_in[6];
    const float* sWd = (const float*)d_in[7];
    const float* sgw = (const float*)d_in[8];
    float* out = (float*)d_out;
    (void)in_sizes; (void)n_in; (void)out_size;

    // No static guards — identical work on every call (harness rule).
    cudaFuncSetAttribute(k_upgate, cudaFuncAttributeMaxDynamicSharedMemorySize, U_SMEM);
    cudaFuncSetAttribute(k_down,   cudaFuncAttributeMaxDynamicSharedMemorySize, D_SMEM);

    float *xr, *wgr, *wur, *wdr, *swgr, *swur, *swdr;
    cudaGetSymbolAddress((void**)&xr,   g_Xr);
    cudaGetSymbolAddress((void**)&wgr,  g_Wgr);
    cudaGetSymbolAddress((void**)&wur,  g_Wur);
    cudaGetSymbolAddress((void**)&wdr,  g_Wdr);
    cudaGetSymbolAddress((void**)&swgr, g_sWgr);
    cudaGetSymbolAddress((void**)&swur, g_sWur);
    cudaGetSymbolAddress((void**)&swdr, g_sWdr);

    const int EW4 = ENUM * DDIM * FDIM / 4;   // 4.19M float4
    const int SW4 = DDIM * FDIM / 4;
    const int XN4 = TNUM * DDIM / 4;
    k_cvt<<<(XN4 + 255) / 256, 256>>>((const float4*)x,   (float4*)xr,   XN4);
    k_cvt<<<(EW4 + 255) / 256, 256>>>((const float4*)Wg,  (float4*)wgr,  EW4);
    k_cvt<<<(EW4 + 255) / 256, 256>>>((const float4*)Wu,  (float4*)wur,  EW4);
    k_cvt<<<(EW4 + 255) / 256, 256>>>((const float4*)Wd,  (float4*)wdr,  EW4);
    k_cvt<<<(SW4 + 255) / 256, 256>>>((const float4*)sWg, (float4*)swgr, SW4);
    k_cvt<<<(SW4 + 255) / 256, 256>>>((const float4*)sWu, (float4*)swur, SW4);
    k_cvt<<<(SW4 + 255) / 256, 256>>>((const float4*)sWd, (float4*)swdr, SW4);

    k_init<<<8, 256>>>();
    k_router<<<TNUM, 128>>>(x, gw, sgw);
    k_scan<<<1, 1>>>();
    k_scatter<<<(TNUM * TOPK + 255) / 256, 256>>>();

    k_upgate<<<dim3(MAXT, FDIM / 64), 256, U_SMEM>>>();
    k_down<<<dim3(MAXT, DDIM / 128), 256, D_SMEM>>>();
    k_combine<<<TNUM, 256>>>(out);
}